// round 2
// baseline (speedup 1.0000x reference)
#include <cuda_runtime.h>
#include <cstdint>

// Problem constants (fixed shapes for CatmullRomActivation_52956946760055)
#define MM 16384
#define DD 1024
#define NN 1024
#define KCP 34

// Packed fp32x2 FMA (Blackwell sm_100+; doubles fp32 FMA throughput vs scalar FFMA)
#define FMA2(d, a, b) \
    asm("fma.rn.f32x2 %0, %1, %2, %0;" : "+l"(d) : "l"(a), "l"(b))
#define PACK2(d, lo, hi) \
    asm("mov.b64 %0, {%1, %2};" : "=l"(d) : "r"(__float_as_uint(lo)), "r"(__float_as_uint(hi)))
#define UNPACK2(lo, hi, d) \
    asm("mov.b64 {%0, %1}, %2;" : "=r"(lo), "=r"(hi) : "l"(d))

__device__ __forceinline__ float spline_eval(float s, const float* __restrict__ q)
{
    // u = frac(s / 0.25)
    float t = s * 4.0f;
    float u = t - floorf(t);
    // p0 = floor((s + 4) * 30/8 + 1), clamped per reference
    float pf = floorf((s + 4.0f) * 3.75f + 1.0f);
    if (s <= -4.0f) pf = 1.0f;
    if (s >=  4.0f) pf = 31.0f;
    int p0 = (int)pf;
    p0 = max(1, min(31, p0));
    float Q0 = q[p0 - 1];
    float Q1 = q[p0];
    float Q2 = q[p0 + 1];
    float Q3 = q[p0 + 2];
    float c3 = 3.0f * (Q1 - Q2) + (Q3 - Q0);
    float c2 = 2.0f * Q0 - 5.0f * Q1 + 4.0f * Q2 - Q3;
    float c1 = Q2 - Q0;
    float c0 = 2.0f * Q1;
    return 0.5f * (((c3 * u + c2) * u + c1) * u + c0);
}

__global__ __launch_bounds__(256, 2)
void catmullrom_fused_kernel(const float* __restrict__ A,   // X  [M, D]
                             const float* __restrict__ B,   // W  [D, N]
                             const float* __restrict__ CP,  // control points [N, 34]
                             float* __restrict__ out)       // [M, N]
{
    __shared__ float As[16][132];   // transposed A tile, padded stride
    __shared__ float Bs[16][128];
    __shared__ float cps[128][35];  // control points for this block's 128 neurons

    const int tid = threadIdx.x;
    const int tx = tid & 15;        // column group (N dir)
    const int ty = tid >> 4;        // row group (M dir)
    const int m0 = blockIdx.y * 128;
    const int n0 = blockIdx.x * 128;

    // Stage control points for the block's neuron columns
    for (int idx = tid; idx < 128 * KCP; idx += 256) {
        int c = idx / KCP;
        int k = idx - c * KCP;
        cps[c][k] = CP[(n0 + c) * KCP + k];
    }

    // Global-load assignments (float4 granularity)
    const int arow = tid >> 2;      // 0..63   (A tile row)
    const int ac4  = tid & 3;       // 0..3    (A tile float4 within the 16-k row)
    const int brow = tid >> 5;      // 0..7    (B tile k-row)
    const int bc4  = tid & 31;      // 0..31   (B tile float4 along N)

    const float* Aptr  = A + (m0 + arow) * DD + ac4 * 4;
    const float* Aptr2 = Aptr + 64 * DD;
    const float* Bptr  = B + brow * NN + n0 + bc4 * 4;
    const float* Bptr2 = Bptr + 8 * NN;

    // Prefetch tile 0 into registers
    float4 ra0 = *reinterpret_cast<const float4*>(Aptr);
    float4 ra1 = *reinterpret_cast<const float4*>(Aptr2);
    float4 rb0 = *reinterpret_cast<const float4*>(Bptr);
    float4 rb1 = *reinterpret_cast<const float4*>(Bptr2);

    unsigned long long acc[8][4];
    #pragma unroll
    for (int i = 0; i < 8; ++i)
        #pragma unroll
        for (int j = 0; j < 4; ++j)
            acc[i][j] = 0ull;

    const int NKT = DD / 16;  // 64 k-tiles
    for (int kt = 0; kt < NKT; ++kt) {
        // Commit staged registers to SMEM (transpose A)
        As[ac4 * 4 + 0][arow]      = ra0.x;
        As[ac4 * 4 + 1][arow]      = ra0.y;
        As[ac4 * 4 + 2][arow]      = ra0.z;
        As[ac4 * 4 + 3][arow]      = ra0.w;
        As[ac4 * 4 + 0][arow + 64] = ra1.x;
        As[ac4 * 4 + 1][arow + 64] = ra1.y;
        As[ac4 * 4 + 2][arow + 64] = ra1.z;
        As[ac4 * 4 + 3][arow + 64] = ra1.w;
        *reinterpret_cast<float4*>(&Bs[brow][bc4 * 4])     = rb0;
        *reinterpret_cast<float4*>(&Bs[brow + 8][bc4 * 4]) = rb1;
        __syncthreads();

        // Prefetch next k-tile while computing this one
        if (kt < NKT - 1) {
            ra0 = *reinterpret_cast<const float4*>(Aptr  + (kt + 1) * 16);
            ra1 = *reinterpret_cast<const float4*>(Aptr2 + (kt + 1) * 16);
            rb0 = *reinterpret_cast<const float4*>(Bptr  + (kt + 1) * 16 * NN);
            rb1 = *reinterpret_cast<const float4*>(Bptr2 + (kt + 1) * 16 * NN);
        }

        #pragma unroll
        for (int kk = 0; kk < 16; ++kk) {
            float4 af0 = *reinterpret_cast<const float4*>(&As[kk][ty * 8]);
            float4 af1 = *reinterpret_cast<const float4*>(&As[kk][ty * 8 + 4]);
            float4 bf0 = *reinterpret_cast<const float4*>(&Bs[kk][tx * 8]);
            float4 bf1 = *reinterpret_cast<const float4*>(&Bs[kk][tx * 8 + 4]);

            unsigned long long bp[4];
            PACK2(bp[0], bf0.x, bf0.y);
            PACK2(bp[1], bf0.z, bf0.w);
            PACK2(bp[2], bf1.x, bf1.y);
            PACK2(bp[3], bf1.z, bf1.w);

            float av[8] = {af0.x, af0.y, af0.z, af0.w, af1.x, af1.y, af1.z, af1.w};
            #pragma unroll
            for (int i = 0; i < 8; ++i) {
                unsigned long long ap;
                PACK2(ap, av[i], av[i]);
                #pragma unroll
                for (int j = 0; j < 4; ++j)
                    FMA2(acc[i][j], ap, bp[j]);
            }
        }
        __syncthreads();
    }

    // Epilogue: spline activation + store
    #pragma unroll
    for (int i = 0; i < 8; ++i) {
        const int gm = m0 + ty * 8 + i;
        float vals[8];
        #pragma unroll
        for (int j4 = 0; j4 < 4; ++j4) {
            unsigned int lo, hi;
            UNPACK2(lo, hi, acc[i][j4]);
            vals[2 * j4]     = __uint_as_float(lo);
            vals[2 * j4 + 1] = __uint_as_float(hi);
        }
        float res[8];
        #pragma unroll
        for (int j = 0; j < 8; ++j) {
            const int cl = tx * 8 + j;           // local neuron column
            res[j] = spline_eval(vals[j], &cps[cl][0]);
        }
        float4 o0 = make_float4(res[0], res[1], res[2], res[3]);
        float4 o1 = make_float4(res[4], res[5], res[6], res[7]);
        float4* op = reinterpret_cast<float4*>(&out[(size_t)gm * NN + n0 + tx * 8]);
        op[0] = o0;
        op[1] = o1;
    }
}

extern "C" void kernel_launch(void* const* d_in, const int* in_sizes, int n_in,
                              void* d_out, int out_size)
{
    const float* X  = (const float*)d_in[0];
    const float* W  = (const float*)d_in[1];
    const float* CP = (const float*)d_in[2];
    float* out = (float*)d_out;

    dim3 grid(NN / 128, MM / 128);   // (8, 128)
    dim3 block(256);
    catmullrom_fused_kernel<<<grid, block>>>(X, W, CP, out);
}

// round 4
// speedup vs baseline: 1.7524x; 1.7524x over previous
#include <cuda_runtime.h>
#include <cuda_bf16.h>
#include <cstdint>

#define MM 16384
#define DD 1024
#define NN 1024
#define KCP 34

// Split-bf16 operands: [row][kblock(32)][32 hi | 32 lo] bf16
__device__ __nv_bfloat16 A2_buf[(size_t)MM * 2 * DD];   // 64 MB
__device__ __nv_bfloat16 B2_buf[(size_t)NN * 2 * DD];   // 4 MB (B transposed to [n][k])

__device__ __forceinline__ uint32_t s2u(const void* p) {
    uint32_t a;
    asm("{ .reg .u64 t; cvta.to.shared.u64 t, %1; cvt.u32.u64 %0, t; }" : "=r"(a) : "l"(p));
    return a;
}

#define LDSM4(r, a) \
    asm volatile("ldmatrix.sync.aligned.m8n8.x4.shared.b16 {%0,%1,%2,%3}, [%4];" \
                 : "=r"((r)[0]), "=r"((r)[1]), "=r"((r)[2]), "=r"((r)[3]) : "r"(a))

#define MMA16816(c, a, b0, b1) \
    asm volatile("mma.sync.aligned.m16n8k16.row.col.f32.bf16.bf16.f32 " \
                 "{%0,%1,%2,%3}, {%4,%5,%6,%7}, {%8,%9}, {%0,%1,%2,%3};" \
                 : "+f"((c).x), "+f"((c).y), "+f"((c).z), "+f"((c).w) \
                 : "r"((a)[0]), "r"((a)[1]), "r"((a)[2]), "r"((a)[3]), "r"(b0), "r"(b1))

#define CPASYNC16(d, s) \
    asm volatile("cp.async.cg.shared.global [%0], [%1], 16;" :: "r"(d), "l"(s))

// ---------------- convert kernels ----------------
__global__ __launch_bounds__(256) void convert_A(const float* __restrict__ X) {
    int t = blockIdx.x * blockDim.x + threadIdx.x;     // MM*DD/2 threads
    int m = t >> 9;
    int k = (t & 511) * 2;
    float2 v = *reinterpret_cast<const float2*>(X + (size_t)m * DD + k);
    __nv_bfloat16 h0 = __float2bfloat16(v.x);
    __nv_bfloat16 h1 = __float2bfloat16(v.y);
    __nv_bfloat16 l0 = __float2bfloat16(v.x - __bfloat162float(h0));
    __nv_bfloat16 l1 = __float2bfloat16(v.y - __bfloat162float(h1));
    int kb = k >> 5, j = k & 31;
    size_t base = ((size_t)m * 32 + kb) * 64;
    __nv_bfloat162 hh; hh.x = h0; hh.y = h1;
    __nv_bfloat162 ll; ll.x = l0; ll.y = l1;
    *reinterpret_cast<__nv_bfloat162*>(A2_buf + base + j)      = hh;
    *reinterpret_cast<__nv_bfloat162*>(A2_buf + base + 32 + j) = ll;
}

__global__ __launch_bounds__(256) void convert_B(const float* __restrict__ W) {
    int t = blockIdx.x * blockDim.x + threadIdx.x;     // DD*NN threads
    int k = t >> 10;
    int n = t & 1023;
    float v = W[(size_t)k * NN + n];
    __nv_bfloat16 h = __float2bfloat16(v);
    __nv_bfloat16 l = __float2bfloat16(v - __bfloat162float(h));
    int kb = k >> 5, j = k & 31;
    size_t base = ((size_t)n * 32 + kb) * 64;
    B2_buf[base + j]      = h;
    B2_buf[base + 32 + j] = l;
}

// ---------------- fused GEMM + spline ----------------
// SMEM: cps 128*35*4 = 17920 B, then 4 A stages (18432 B each), 4 B stages.
#define STAGE_BYTES 18432          // 128 rows * 144 B (128 data + 16 pad)
#define SOFF_STAGES 17920
#define SMEM_TOTAL  (SOFF_STAGES + 8 * STAGE_BYTES)   // 165376

__device__ __forceinline__ float spline_eval(float s, const float* __restrict__ q)
{
    float t = s * 4.0f;
    float u = t - floorf(t);
    float pf = floorf((s + 4.0f) * 3.75f + 1.0f);
    if (s <= -4.0f) pf = 1.0f;
    if (s >=  4.0f) pf = 31.0f;
    int p0 = (int)pf;
    p0 = max(1, min(31, p0));
    float Q0 = q[p0 - 1];
    float Q1 = q[p0];
    float Q2 = q[p0 + 1];
    float Q3 = q[p0 + 2];
    float c3 = 3.0f * (Q1 - Q2) + (Q3 - Q0);
    float c2 = 2.0f * Q0 - 5.0f * Q1 + 4.0f * Q2 - Q3;
    float c1 = Q2 - Q0;
    float c0 = 2.0f * Q1;
    return 0.5f * (((c3 * u + c2) * u + c1) * u + c0);
}

__device__ __forceinline__ void load_stage(uint32_t aBase, uint32_t bBase, int s, int c,
                                           const __nv_bfloat16* Ag, const __nv_bfloat16* Bg,
                                           int tid)
{
    const uint32_t dA = aBase + s * STAGE_BYTES;
    const uint32_t dB = bBase + s * STAGE_BYTES;
    #pragma unroll
    for (int i = 0; i < 4; ++i) {
        int chunk = tid + i * 256;
        int r = chunk >> 3, col = chunk & 7;
        const size_t src = (size_t)r * 2048 + (size_t)c * 64 + col * 8;
        CPASYNC16(dA + r * 144 + col * 16, (const char*)(Ag + src));
        CPASYNC16(dB + r * 144 + col * 16, (const char*)(Bg + src));
    }
}

__global__ __launch_bounds__(256, 1) void gemm_spline(const float* __restrict__ CP,
                                                      float* __restrict__ out)
{
    extern __shared__ char smem[];
    float* cps = reinterpret_cast<float*>(smem);
    const uint32_t su = s2u(smem);
    const uint32_t aBase = su + SOFF_STAGES;
    const uint32_t bBase = su + SOFF_STAGES + 4 * STAGE_BYTES;

    const int tid  = threadIdx.x;
    const int lane = tid & 31;
    const int wid  = tid >> 5;
    const int bx = blockIdx.x;   // n tile (0..7)
    const int by = blockIdx.y;   // m tile (0..127)

    // stage control points (128 neurons, padded stride 35)
    for (int i = tid; i < 128 * KCP; i += 256) {
        int c = i / KCP, k = i - c * KCP;
        cps[c * 35 + k] = CP[(size_t)(bx * 128 + c) * KCP + k];
    }

    const __nv_bfloat16* Ag = A2_buf + (size_t)by * 128 * 2048;
    const __nv_bfloat16* Bg = B2_buf + (size_t)bx * 128 * 2048;

    // prologue: stages 0..2
    #pragma unroll
    for (int c = 0; c < 3; ++c) {
        load_stage(aBase, bBase, c, c, Ag, Bg, tid);
        asm volatile("cp.async.commit_group;" ::: "memory");
    }

    float4 acc[4][4];
    #pragma unroll
    for (int i = 0; i < 4; ++i)
        #pragma unroll
        for (int j = 0; j < 4; ++j)
            acc[i][j] = make_float4(0.f, 0.f, 0.f, 0.f);

    const int mw = (wid >> 2) * 64;
    const int nw = (wid & 3) * 32;
    const int lrow = lane & 15;
    const int lcol = lane >> 4;

    #pragma unroll 1
    for (int c = 0; c < 32; ++c) {
        asm volatile("cp.async.wait_group 2;" ::: "memory");
        __syncthreads();
        if (c + 3 < 32)
            load_stage(aBase, bBase, (c + 3) & 3, c + 3, Ag, Bg, tid);
        asm volatile("cp.async.commit_group;" ::: "memory");

        const int s = c & 3;
        const uint32_t aRow = aBase + s * STAGE_BYTES + (mw + lrow) * 144 + lcol * 16;
        const uint32_t bRow = bBase + s * STAGE_BYTES + (nw + lrow) * 144 + lcol * 16;

        #pragma unroll
        for (int ks = 0; ks < 2; ++ks) {
            uint32_t Ah[4][4], Al[4][4], Bh[2][4], Bl[2][4];
            #pragma unroll
            for (int mf = 0; mf < 4; ++mf) {
                LDSM4(Ah[mf], aRow + mf * (16 * 144) + ks * 32);
                LDSM4(Al[mf], aRow + mf * (16 * 144) + ks * 32 + 64);
            }
            #pragma unroll
            for (int g = 0; g < 2; ++g) {
                LDSM4(Bh[g], bRow + g * (16 * 144) + ks * 32);
                LDSM4(Bl[g], bRow + g * (16 * 144) + ks * 32 + 64);
            }
            #pragma unroll
            for (int mf = 0; mf < 4; ++mf)
                #pragma unroll
                for (int nf = 0; nf < 4; ++nf) {
                    const int g = nf >> 1, w = nf & 1;
                    MMA16816(acc[mf][nf], Ah[mf], Bh[g][w], Bh[g][w + 2]);   // hi*hi
                    MMA16816(acc[mf][nf], Al[mf], Bh[g][w], Bh[g][w + 2]);   // lo*hi
                    MMA16816(acc[mf][nf], Ah[mf], Bl[g][w], Bl[g][w + 2]);   // hi*lo
                }
        }
    }

    // epilogue: spline + store
    #pragma unroll
    for (int mf = 0; mf < 4; ++mf) {
        const int row0 = mw + mf * 16 + (lane >> 2);
        const size_t g0 = (size_t)(by * 128 + row0) * NN + bx * 128;
        const size_t g1 = g0 + 8 * NN;
        #pragma unroll
        for (int nf = 0; nf < 4; ++nf) {
            const int cl = nw + nf * 8 + 2 * (lane & 3);
            const float* q0 = &cps[cl * 35];
            const float* q1 = &cps[(cl + 1) * 35];
            float2 o0, o1;
            o0.x = spline_eval(acc[mf][nf].x, q0);
            o0.y = spline_eval(acc[mf][nf].y, q1);
            o1.x = spline_eval(acc[mf][nf].z, q0);
            o1.y = spline_eval(acc[mf][nf].w, q1);
            *reinterpret_cast<float2*>(out + g0 + cl) = o0;
            *reinterpret_cast<float2*>(out + g1 + cl) = o1;
        }
    }
}

extern "C" void kernel_launch(void* const* d_in, const int* in_sizes, int n_in,
                              void* d_out, int out_size)
{
    const float* X  = (const float*)d_in[0];
    const float* W  = (const float*)d_in[1];
    const float* CP = (const float*)d_in[2];
    float* out = (float*)d_out;

    cudaFuncSetAttribute(gemm_spline, cudaFuncAttributeMaxDynamicSharedMemorySize, SMEM_TOTAL);

    convert_A<<<(MM * DD / 2) / 256, 256>>>(X);
    convert_B<<<(DD * NN) / 256, 256>>>(W);

    dim3 grid(NN / 128, MM / 128);   // (8, 128)
    gemm_spline<<<grid, 256, SMEM_TOTAL>>>(CP, out);
}